// round 8
// baseline (speedup 1.0000x reference)
#include <cuda_runtime.h>
#include <cuda_fp16.h>
#include <cstdint>

#define BATCH 8
#define SEQ   2048
#define DIM   1024
#define NST   256
#define HID   512
#define NEXP  8
#define NTOK  (BATCH*SEQ)   // 16384

// ---------------- device scratch (static, allocation-free) ----------------
__device__ __half g_xgh[NTOK*DIM], g_xgl[NTOK*DIM];        // x gathered, split
__device__ __half g_Winh [NEXP*NST*DIM];
__device__ __half g_Wsinh[NEXP*HID*DIM];
__device__ __half g_Wsoh [NEXP*4*NST*HID];
__device__ __half g_Woth [NEXP*DIM*NST];
__device__ __half g_shh[NTOK*HID], g_shl[NTOK*HID];        // silu out, split
__device__ __half g_yh [NTOK*NST], g_yl [NTOK*NST];        // scan out, split
__device__ float g_u [NTOK*NST];
__device__ float g_a [NTOK*NST], g_bu[NTOK*NST], g_c[NTOK*NST], g_sk[NTOK*NST];
__device__ int g_list[NTOK];
__device__ int g_tileCnt[64][NEXP];
__device__ int g_tileOff[64][NEXP];
__device__ int g_eBase[NEXP];
__device__ int g_cnt[NEXP];
__device__ int g_beOff[BATCH][NEXP];
__device__ int g_beCnt[BATCH][NEXP];

__device__ __forceinline__ float sigmoidf_(float x){ return 1.f/(1.f+__expf(-x)); }

__device__ __forceinline__ uint32_t smem_u32(const void* p){
    uint32_t a;
    asm("{ .reg .u64 t; cvta.to.shared.u64 t, %1; cvt.u32.u64 %0, t; }" : "=r"(a) : "l"(p));
    return a;
}
__device__ __forceinline__ void ldsm_x4(uint32_t* r, uint32_t addr){
    asm volatile("ldmatrix.sync.aligned.m8n8.x4.shared.b16 {%0,%1,%2,%3}, [%4];"
        : "=r"(r[0]),"=r"(r[1]),"=r"(r[2]),"=r"(r[3]) : "r"(addr));
}
__device__ __forceinline__ void mma16816h(float* d, const uint32_t* a, uint32_t b0, uint32_t b1){
    asm volatile("mma.sync.aligned.m16n8k16.row.col.f32.f16.f16.f32 "
        "{%0,%1,%2,%3}, {%4,%5,%6,%7}, {%8,%9}, {%0,%1,%2,%3};"
        : "+f"(d[0]),"+f"(d[1]),"+f"(d[2]),"+f"(d[3])
        : "r"(a[0]),"r"(a[1]),"r"(a[2]),"r"(a[3]), "r"(b0),"r"(b1));
}
__device__ __forceinline__ uint32_t h2bits(__half2 h){ return *reinterpret_cast<uint32_t*>(&h); }
__device__ __forceinline__ int route_of(int tokid){
    unsigned x = (unsigned)tokid;
    x ^= x >> 16; x *= 2246822507u;
    x ^= x >> 13; x *= 3266489909u;
    x ^= x >> 16;
    return (int)(x & 7u);
}

// ---------------- deterministic routing (count / offset / place) ----------
__global__ void count_kernel(const int* __restrict__ tok){
    int blk = blockIdx.x, tid = threadIdx.x, wid = tid>>5, lane = tid&31;
    int r = route_of(tok[blk*256 + tid]);
    __shared__ int wcnt[8][8];
    unsigned m[8];
    #pragma unroll
    for (int e = 0; e < 8; e++) m[e] = __ballot_sync(0xffffffffu, r == e);
    if (lane < 8) wcnt[wid][lane] = __popc(m[lane]);
    __syncthreads();
    if (tid < 8){
        int s = 0;
        #pragma unroll
        for (int w = 0; w < 8; w++) s += wcnt[w][tid];
        g_tileCnt[blk][tid] = s;
    }
}
__global__ void offset_kernel(){
    __shared__ int tot[8];
    int tid = threadIdx.x;
    if (tid < 8){
        int run = 0;
        for (int t = 0; t < 64; t++){ g_tileOff[t][tid] = run; run += g_tileCnt[t][tid]; }
        tot[tid] = run;
    }
    __syncthreads();
    if (tid == 0){
        int base = 0;
        for (int e = 0; e < 8; e++){ g_eBase[e] = base; g_cnt[e] = tot[e]; base += tot[e]; }
    }
    __syncthreads();
    if (tid < 8){
        for (int t = 0; t < 64; t++) g_tileOff[t][tid] += g_eBase[tid];
        for (int b = 0; b < 8; b++){
            int s = 0;
            for (int k = 0; k < 8; k++) s += g_tileCnt[b*8+k][tid];
            g_beOff[b][tid] = g_tileOff[b*8][tid];
            g_beCnt[b][tid] = s;
        }
    }
}
__global__ void place_kernel(const int* __restrict__ tok){
    int blk = blockIdx.x, tid = threadIdx.x, wid = tid>>5, lane = tid&31;
    int t = blk*256 + tid;
    int r = route_of(tok[t]);
    __shared__ int wcnt[8][8];
    unsigned m[8];
    #pragma unroll
    for (int e = 0; e < 8; e++) m[e] = __ballot_sync(0xffffffffu, r == e);
    if (lane < 8) wcnt[wid][lane] = __popc(m[lane]);
    __syncthreads();
    int base = 0;
    for (int w = 0; w < wid; w++) base += wcnt[w][r];
    int rank = base + __popc(m[r] & ((1u << lane) - 1u));
    g_list[g_tileOff[blk][r] + rank] = t;
}

// ---------------- conversions ----------------
// weights: fp32 -> fp16 hi (rounding err ~2^-12, within budget)
__global__ void __launch_bounds__(256)
cvt_w(const float* __restrict__ src, __half* __restrict__ dst, int n4){
    int i = blockIdx.x*blockDim.x + threadIdx.x;
    if (i >= n4) return;
    float4 v = reinterpret_cast<const float4*>(src)[i];
    reinterpret_cast<uint2*>(dst)[i] =
        make_uint2(h2bits(__floats2half2_rn(v.x, v.y)), h2bits(__floats2half2_rn(v.z, v.w)));
}
// x: gather into expert-compact order + split hi/lo
__global__ void __launch_bounds__(256)
cvt_x(const float* __restrict__ x){
    const int pos = blockIdx.x;
    const int i   = threadIdx.x;               // float4 index within row (256)
    const int tok = g_list[pos];
    float4 v = reinterpret_cast<const float4*>(x)[(size_t)tok*256 + i];
    __half2 h0 = __floats2half2_rn(v.x, v.y);
    __half2 h1 = __floats2half2_rn(v.z, v.w);
    __half2 l0 = __floats2half2_rn(v.x - __half2float(__low2half(h0)),
                                   v.y - __half2float(__high2half(h0)));
    __half2 l1 = __floats2half2_rn(v.z - __half2float(__low2half(h1)),
                                   v.w - __half2float(__high2half(h1)));
    reinterpret_cast<uint2*>(g_xgh)[(size_t)pos*256 + i] = make_uint2(h2bits(h0), h2bits(h1));
    reinterpret_cast<uint2*>(g_xgl)[(size_t)pos*256 + i] = make_uint2(h2bits(l0), h2bits(l1));
}

// ---------------- grouped GEMM: 64x128 tile, fp16x2 mma, 128 threads ------
// C = A . W[e]^T ; A rows compact (pre-gathered), fp16 hi/lo; W fp16 hi.
// MODE: 0 u, 1 silu->sh(h/l), 2 gates, 3 out proj (scatter via g_list)
#define SSTR   80                 // 32 fp16 padded to 40 (80 B)
#define ATILE  (64*SSTR)          // 5120
#define BTILE  (128*SSTR)         // 10240
#define STAGE  (2*ATILE + BTILE)  // 20480 : Ah | Al | Bh
// 2 stages = 40960 static smem

template<int MODE>
__global__ void __launch_bounds__(128, 3)
gemm_mma(const __half* __restrict__ Ah, const __half* __restrict__ Al,
         const __half* __restrict__ Wh,
         const float* __restrict__ dparam, float* __restrict__ outp,
         int K, int nout)
{
    const int e   = blockIdx.z;
    const int cnt = g_cnt[e];
    const int n0  = blockIdx.y * 128;
    const int posBase = g_eBase[e];
    const __half* __restrict__ W = Wh + (size_t)e * nout * K;

    __shared__ __align__(16) char sm[2*STAGE];

    const int tid  = threadIdx.x;
    const int wid  = tid >> 5;
    const int lane = tid & 31;
    const int NC   = K >> 5;

    // loader mapping
    const int arow = tid >> 1;            // 0..63
    const int aseg = (tid & 1) * 16;      // fp16 elems (32B half-row)
    const int aoff = arow*SSTR + aseg*2;  // STS byte offset in A tiles
    const __half* bp = W + (size_t)(n0 + tid)*K;   // B: one full row per thread
    const int boff = tid*SSTR;

    const uint32_t sb = smem_u32(sm);
    const int wm = wid & 1, wn = wid >> 1;
    const uint32_t a_base = sb + (uint32_t)((wm*32 + (lane & 15))*SSTR + (lane >> 4)*16);
    const uint32_t b_base = sb + 2*ATILE +
        (uint32_t)((wn*64 + (lane >> 4)*8 + (lane & 7))*SSTR + ((lane >> 3) & 1)*16);

    for (int m0 = blockIdx.x * 64; m0 < cnt; m0 += 2048){
        // per-m-iter A pointers (clamped)
        int am = m0 + arow; if (am >= cnt) am = cnt - 1;
        const __half* apH = Ah + (size_t)(posBase + am)*K + aseg;
        const __half* apL = Al + (size_t)(posBase + am)*K + aseg;

        float acc[2][8][4];
        #pragma unroll
        for (int mi=0;mi<2;mi++)
            #pragma unroll
            for (int ni=0;ni<8;ni++)
                #pragma unroll
                for (int q=0;q<4;q++) acc[mi][ni][q]=0.f;

        uint4 ra[2], rl[2], rb[4];
        ra[0]=*(const uint4*)(apH);   ra[1]=*(const uint4*)(apH+8);
        rl[0]=*(const uint4*)(apL);   rl[1]=*(const uint4*)(apL+8);
        #pragma unroll
        for (int q = 0; q < 4; q++) rb[q]=*(const uint4*)(bp + q*8);

        for (int c = 0; c < NC; c++){
            __syncthreads();
            {
                char* d = sm + (c & 1)*STAGE;
                *(uint4*)(d + aoff)            = ra[0];
                *(uint4*)(d + aoff + 16)       = ra[1];
                *(uint4*)(d + ATILE + aoff)    = rl[0];
                *(uint4*)(d + ATILE + aoff+16) = rl[1];
                char* db = d + 2*ATILE + boff;
                *(uint4*)(db)      = rb[0];
                *(uint4*)(db + 16) = rb[1];
                *(uint4*)(db + 32) = rb[2];
                *(uint4*)(db + 48) = rb[3];
            }
            __syncthreads();
            if (c + 1 < NC){
                const int k1 = (c + 1) << 5;
                ra[0]=*(const uint4*)(apH+k1);   ra[1]=*(const uint4*)(apH+k1+8);
                rl[0]=*(const uint4*)(apL+k1);   rl[1]=*(const uint4*)(apL+k1+8);
                #pragma unroll
                for (int q = 0; q < 4; q++) rb[q]=*(const uint4*)(bp + k1 + q*8);
            }
            const uint32_t ab = a_base + (c & 1)*STAGE;
            const uint32_t bb = b_base + (c & 1)*STAGE;
            #pragma unroll
            for (int ks = 0; ks < 2; ks++){
                uint32_t ah[2][4], al[2][4], bh[4][4];
                #pragma unroll
                for (int mi = 0; mi < 2; mi++){
                    uint32_t ad = ab + mi*16*SSTR + ks*32;
                    ldsm_x4(ah[mi], ad);
                    ldsm_x4(al[mi], ad + ATILE);
                }
                #pragma unroll
                for (int np = 0; np < 4; np++)
                    ldsm_x4(bh[np], bb + np*16*SSTR + ks*32);
                #pragma unroll
                for (int mi = 0; mi < 2; mi++)
                    #pragma unroll
                    for (int ni = 0; ni < 8; ni++){
                        const int np = ni >> 1, h = (ni & 1)*2;
                        mma16816h(acc[mi][ni], ah[mi], bh[np][h], bh[np][h+1]);
                        mma16816h(acc[mi][ni], al[mi], bh[np][h], bh[np][h+1]);
                    }
            }
        }

        // ---- epilogue
        const int sec = (MODE == 2) ? ((n0 + wn*64) >> 8) : 0;
        #pragma unroll
        for (int mi = 0; mi < 2; mi++){
            const int rt0 = wm*32 + mi*16 + (lane >> 2);
            #pragma unroll
            for (int hf = 0; hf < 2; hf++){
                const int rt = rt0 + hf*8;
                const int m  = m0 + rt;
                if (m >= cnt) continue;
                const int pos = posBase + m;
                #pragma unroll
                for (int ni = 0; ni < 8; ni++){
                    float v0 = acc[mi][ni][hf*2], v1 = acc[mi][ni][hf*2+1];
                    const int col = n0 + wn*64 + (ni>>1)*16 + (ni&1)*8 + (lane&3)*2;
                    if (MODE == 0){
                        *(float2*)(g_u + (size_t)pos*NST + col) = make_float2(v0, v1);
                    } else if (MODE == 1){
                        float s0 = v0*sigmoidf_(v0), s1 = v1*sigmoidf_(v1);
                        __half2 hh = __floats2half2_rn(s0, s1);
                        __half2 ll = __floats2half2_rn(s0 - __half2float(__low2half(hh)),
                                                       s1 - __half2float(__high2half(hh)));
                        *reinterpret_cast<uint32_t*>(g_shh + (size_t)pos*HID + col) = h2bits(hh);
                        *reinterpret_cast<uint32_t*>(g_shl + (size_t)pos*HID + col) = h2bits(ll);
                    } else if (MODE == 2){
                        const int off = col & 255;
                        const size_t base = (size_t)pos*NST + off;
                        if (sec == 0){
                            *(float2*)(g_a + base) = make_float2(sigmoidf_(v0), sigmoidf_(v1));
                        } else if (sec == 1){
                            float2 u2 = *(const float2*)(g_u + base);
                            *(float2*)(g_bu + base) = make_float2(tanhf(v0)*u2.x, tanhf(v1)*u2.y);
                        } else if (sec == 2){
                            *(float2*)(g_c + base) = make_float2(tanhf(v0), tanhf(v1));
                        } else {
                            float2 u2 = *(const float2*)(g_u + base);
                            float2 d2 = *(const float2*)(dparam + e*NST + off);
                            *(float2*)(g_sk + base) =
                                make_float2(sigmoidf_(v0)*d2.x*u2.x, sigmoidf_(v1)*d2.y*u2.y);
                        }
                    } else {
                        const int tok = g_list[pos];
                        *(float2*)(outp + (size_t)tok*DIM + col) = make_float2(v0, v1);
                    }
                }
            }
        }
    }
}

// ---------------- sequential scan, compact streaming, fp16 y out ----------
__global__ void __launch_bounds__(256)
scan_kernel()
{
    const int b = blockIdx.x, e = blockIdx.y, tid = threadIdx.x;
    const int pos0 = g_beOff[b][e];
    const int n    = g_beCnt[b][e];

    float a[2][4], bu[2][4], cc[2][4], sk[2][4];
    #pragma unroll
    for (int j = 0; j < 4; j++){
        bool v = j < n;
        size_t idx = ((size_t)(pos0 + (v ? j : 0)))*NST + tid;
        a [0][j] = v ? g_a [idx] : 0.f;
        bu[0][j] = v ? g_bu[idx] : 0.f;
        cc[0][j] = v ? g_c [idx] : 0.f;
        sk[0][j] = v ? g_sk[idx] : 0.f;
    }

    float h = 0.f;
    int cur = 0;
    for (int base = 0; base < n; base += 4){
        const int nxt = cur ^ 1;
        #pragma unroll
        for (int j = 0; j < 4; j++){
            int i = base + 4 + j;
            if (i < n){
                size_t idx = ((size_t)(pos0 + i))*NST + tid;
                a [nxt][j] = g_a [idx];
                bu[nxt][j] = g_bu[idx];
                cc[nxt][j] = g_c [idx];
                sk[nxt][j] = g_sk[idx];
            }
        }
        #pragma unroll
        for (int j = 0; j < 4; j++){
            int i = base + j;
            if (i < n){
                h = fmaf(a[cur][j], h, bu[cur][j]);
                float y = fmaf(cc[cur][j], h, sk[cur][j]);
                size_t idx = ((size_t)(pos0 + i))*NST + tid;
                __half yh = __float2half(y);
                g_yh[idx] = yh;
                g_yl[idx] = __float2half(y - __half2float(yh));
            }
        }
        cur = nxt;
    }
}

// ---------------- launch ----------------
extern "C" void kernel_launch(void* const* d_in, const int* in_sizes, int n_in,
                              void* d_out, int out_size)
{
    const float* x     = (const float*)d_in[0];
    const int*   tok   = (const int*)  d_in[1];
    const float* Win   = (const float*)d_in[2];
    const float* Wsin  = (const float*)d_in[3];
    const float* Wsout = (const float*)d_in[4];
    const float* Wout  = (const float*)d_in[5];
    const float* dpar  = (const float*)d_in[6];
    float* outp = (float*)d_out;
    (void)in_sizes; (void)n_in; (void)out_size;

    __half *xgh, *xgl, *winh, *wsih, *wsoh, *woth, *shh, *shl, *yh, *yl;
    cudaGetSymbolAddress((void**)&xgh, g_xgh);  cudaGetSymbolAddress((void**)&xgl, g_xgl);
    cudaGetSymbolAddress((void**)&winh, g_Winh);
    cudaGetSymbolAddress((void**)&wsih, g_Wsinh);
    cudaGetSymbolAddress((void**)&wsoh, g_Wsoh);
    cudaGetSymbolAddress((void**)&woth, g_Woth);
    cudaGetSymbolAddress((void**)&shh, g_shh);  cudaGetSymbolAddress((void**)&shl, g_shl);
    cudaGetSymbolAddress((void**)&yh,  g_yh);   cudaGetSymbolAddress((void**)&yl,  g_yl);

    // routing first (cvt_x gathers by g_list)
    count_kernel <<<64, 256>>>(tok);
    offset_kernel<<<1, 256>>>();
    place_kernel <<<64, 256>>>(tok);

    // conversions
    cvt_w<<<(NEXP*NST*DIM/4 + 255)/256, 256>>>(Win,   winh, NEXP*NST*DIM/4);
    cvt_w<<<(NEXP*HID*DIM/4 + 255)/256, 256>>>(Wsin,  wsih, NEXP*HID*DIM/4);
    cvt_w<<<(NEXP*4*NST*HID/4 + 255)/256, 256>>>(Wsout, wsoh, NEXP*4*NST*HID/4);
    cvt_w<<<(NEXP*DIM*NST/4 + 255)/256, 256>>>(Wout,  woth, NEXP*DIM*NST/4);
    cvt_x<<<NTOK, 256>>>(x);

    dim3 blk(128);
    // u = x . Win^T            (K=1024, nout=256)
    gemm_mma<0><<<dim3(32, 2, NEXP), blk>>>(xgh, xgl, winh, nullptr, nullptr, DIM, NST);
    // sh = silu(x . Wsin^T)    (K=1024, nout=512)
    gemm_mma<1><<<dim3(32, 4, NEXP), blk>>>(xgh, xgl, wsih, nullptr, nullptr, DIM, HID);
    // gates = sh . Wsout^T     (K=512,  nout=1024)
    gemm_mma<2><<<dim3(32, 8, NEXP), blk>>>(shh, shl, wsoh, dpar,    nullptr, HID, 4*NST);
    // recurrence
    scan_kernel<<<dim3(BATCH, NEXP), 256>>>();
    // out = y . Wout^T         (K=256,  nout=1024)
    gemm_mma<3><<<dim3(32, 8, NEXP), blk>>>(yh,  yl,  woth, nullptr, outp,    NST, DIM);
}

// round 9
// speedup vs baseline: 1.5056x; 1.5056x over previous
#include <cuda_runtime.h>
#include <cuda_fp16.h>
#include <cstdint>

#define BATCH 8
#define SEQ   2048
#define DIM   1024
#define NST   256
#define HID   512
#define NEXP  8
#define NTOK  (BATCH*SEQ)   // 16384

// ---------------- device scratch (static, allocation-free) ----------------
__device__ __half g_xg[NTOK*DIM];                // x gathered to expert-compact order, fp16
__device__ __half g_Winh [NEXP*NST*DIM];
__device__ __half g_Wsinh[NEXP*HID*DIM];
__device__ __half g_Wsoh [NEXP*4*NST*HID];
__device__ __half g_Woth [NEXP*DIM*NST];
__device__ __half g_shh[NTOK*HID];               // silu out, fp16, compact
__device__ __half g_yh [NTOK*NST];               // scan out, fp16, compact
__device__ float g_u [NTOK*NST];
__device__ float g_a [NTOK*NST], g_bu[NTOK*NST], g_c[NTOK*NST], g_sk[NTOK*NST];
__device__ int g_list[NTOK];
__device__ int g_tileCnt[64][NEXP];
__device__ int g_tileOff[64][NEXP];
__device__ int g_eBase[NEXP];
__device__ int g_cnt[NEXP];
__device__ int g_beOff[BATCH][NEXP];
__device__ int g_beCnt[BATCH][NEXP];

__device__ __forceinline__ float sigmoidf_(float x){ return 1.f/(1.f+__expf(-x)); }

__device__ __forceinline__ uint32_t smem_u32(const void* p){
    uint32_t a;
    asm("{ .reg .u64 t; cvta.to.shared.u64 t, %1; cvt.u32.u64 %0, t; }" : "=r"(a) : "l"(p));
    return a;
}
__device__ __forceinline__ void ldsm_x4(uint32_t* r, uint32_t addr){
    asm volatile("ldmatrix.sync.aligned.m8n8.x4.shared.b16 {%0,%1,%2,%3}, [%4];"
        : "=r"(r[0]),"=r"(r[1]),"=r"(r[2]),"=r"(r[3]) : "r"(addr));
}
__device__ __forceinline__ void mma16816h(float* d, const uint32_t* a, uint32_t b0, uint32_t b1){
    asm volatile("mma.sync.aligned.m16n8k16.row.col.f32.f16.f16.f32 "
        "{%0,%1,%2,%3}, {%4,%5,%6,%7}, {%8,%9}, {%0,%1,%2,%3};"
        : "+f"(d[0]),"+f"(d[1]),"+f"(d[2]),"+f"(d[3])
        : "r"(a[0]),"r"(a[1]),"r"(a[2]),"r"(a[3]), "r"(b0),"r"(b1));
}
__device__ __forceinline__ uint32_t h2bits(__half2 h){ return *reinterpret_cast<uint32_t*>(&h); }
__device__ __forceinline__ int route_of(int tokid){
    unsigned x = (unsigned)tokid;
    x ^= x >> 16; x *= 2246822507u;
    x ^= x >> 13; x *= 3266489909u;
    x ^= x >> 16;
    return (int)(x & 7u);
}

// ---------------- deterministic routing (count / offset / place) ----------
__global__ void count_kernel(const int* __restrict__ tok){
    int blk = blockIdx.x, tid = threadIdx.x, wid = tid>>5, lane = tid&31;
    int r = route_of(tok[blk*256 + tid]);
    __shared__ int wcnt[8][8];
    unsigned m[8];
    #pragma unroll
    for (int e = 0; e < 8; e++) m[e] = __ballot_sync(0xffffffffu, r == e);
    if (lane < 8) wcnt[wid][lane] = __popc(m[lane]);
    __syncthreads();
    if (tid < 8){
        int s = 0;
        #pragma unroll
        for (int w = 0; w < 8; w++) s += wcnt[w][tid];
        g_tileCnt[blk][tid] = s;
    }
}
__global__ void offset_kernel(){
    __shared__ int tot[8];
    int tid = threadIdx.x;
    if (tid < 8){
        int run = 0;
        for (int t = 0; t < 64; t++){ g_tileOff[t][tid] = run; run += g_tileCnt[t][tid]; }
        tot[tid] = run;
    }
    __syncthreads();
    if (tid == 0){
        int base = 0;
        for (int e = 0; e < 8; e++){ g_eBase[e] = base; g_cnt[e] = tot[e]; base += tot[e]; }
    }
    __syncthreads();
    if (tid < 8){
        for (int t = 0; t < 64; t++) g_tileOff[t][tid] += g_eBase[tid];
        for (int b = 0; b < 8; b++){
            int s = 0;
            for (int k = 0; k < 8; k++) s += g_tileCnt[b*8+k][tid];
            g_beOff[b][tid] = g_tileOff[b*8][tid];
            g_beCnt[b][tid] = s;
        }
    }
}
__global__ void place_kernel(const int* __restrict__ tok){
    int blk = blockIdx.x, tid = threadIdx.x, wid = tid>>5, lane = tid&31;
    int t = blk*256 + tid;
    int r = route_of(tok[t]);
    __shared__ int wcnt[8][8];
    unsigned m[8];
    #pragma unroll
    for (int e = 0; e < 8; e++) m[e] = __ballot_sync(0xffffffffu, r == e);
    if (lane < 8) wcnt[wid][lane] = __popc(m[lane]);
    __syncthreads();
    int base = 0;
    for (int w = 0; w < wid; w++) base += wcnt[w][r];
    int rank = base + __popc(m[r] & ((1u << lane) - 1u));
    g_list[g_tileOff[blk][r] + rank] = t;
}

// ---------------- conversions (once per launch) ----------------
__global__ void __launch_bounds__(256)
cvt_w(const float* __restrict__ src, __half* __restrict__ dst, int n4){
    int i = blockIdx.x*blockDim.x + threadIdx.x;
    if (i >= n4) return;
    float4 v = reinterpret_cast<const float4*>(src)[i];
    reinterpret_cast<uint2*>(dst)[i] =
        make_uint2(h2bits(__floats2half2_rn(v.x, v.y)), h2bits(__floats2half2_rn(v.z, v.w)));
}
// x: gather into expert-compact order + round to fp16
__global__ void __launch_bounds__(256)
cvt_x(const float* __restrict__ x){
    const int pos = blockIdx.x;
    const int i   = threadIdx.x;               // float4 index within row (256 of them)
    const int tok = g_list[pos];
    float4 v = reinterpret_cast<const float4*>(x)[(size_t)tok*256 + i];
    reinterpret_cast<uint2*>(g_xg)[(size_t)pos*256 + i] =
        make_uint2(h2bits(__floats2half2_rn(v.x, v.y)), h2bits(__floats2half2_rn(v.z, v.w)));
}

// ---------------- grouped GEMM: r7 skeleton, pure fp16 operands -----------
// C = A . W[e]^T ; A compact fp16 (pre-gathered), W fp16.
// 256 threads, CTA tile 128x64, warp tile 32x32, single smem buffer +
// register prefetch, 2 CTAs/SM.
// MODE: 0 u, 1 silu->sh(fp16), 2 gates, 3 out proj (scatter via g_list)
#define SSTR   80                 // 32 fp16 padded to 40 (80 B)
#define ATILE  (128*SSTR)         // 10240
#define BTILE  (64*SSTR)          // 5120
// layout: Ah | Bh = 15360 B

template<int MODE>
__global__ void __launch_bounds__(256, 2)
gemm_mma(const __half* __restrict__ A, const __half* __restrict__ Wt,
         const float* __restrict__ dparam, float* __restrict__ outp,
         int K, int nout)
{
    const int e   = blockIdx.z;
    const int cnt = g_cnt[e];
    const int m0  = blockIdx.x * 128;
    if (m0 >= cnt) return;
    const int n0  = blockIdx.y * 64;
    const int posBase = g_eBase[e];
    const __half* __restrict__ W = Wt + (size_t)e * nout * K;

    __shared__ __align__(16) char sm[ATILE + BTILE];

    const int tid  = threadIdx.x;
    const int wid  = tid >> 5;
    const int lane = tid & 31;

    // loader: A rows 0..127, 2 threads/row (32B each); B rows 0..63, 4 threads/row (16B each)
    const int arow = tid >> 1;
    const int acol = (tid & 1) * 16;           // halves
    int am = m0 + arow; if (am >= cnt) am = cnt - 1;
    const __half* ap = A + (size_t)(posBase + am)*K + acol;
    const int aoff = arow*SSTR + acol*2;

    const int brow = tid >> 2;
    const int bcol = (tid & 3) * 8;            // halves
    const __half* bp = W + (size_t)(n0 + brow)*K + bcol;
    const int boff = ATILE + brow*SSTR + bcol*2;

    const uint32_t sb = smem_u32(sm);
    const int wm = wid & 3, wn = wid >> 2;
    const uint32_t a_base = sb + (uint32_t)((wm*32 + (lane & 15))*SSTR + (lane >> 4)*16);
    const uint32_t b_base = sb + ATILE +
        (uint32_t)((wn*32 + (lane >> 4)*8 + (lane & 7))*SSTR + ((lane >> 3) & 1)*16);

    float acc[2][4][4];
    #pragma unroll
    for (int mi=0;mi<2;mi++)
        #pragma unroll
        for (int ni=0;ni<4;ni++)
            #pragma unroll
            for (int q=0;q<4;q++) acc[mi][ni][q]=0.f;

    const int NC = K >> 5;
    uint4 ra0 = *(const uint4*)(ap);
    uint4 ra1 = *(const uint4*)(ap + 8);
    uint4 rb  = *(const uint4*)(bp);

    for (int c = 0; c < NC; c++){
        __syncthreads();   // previous compute finished with smem
        *(uint4*)(sm + aoff)      = ra0;
        *(uint4*)(sm + aoff + 16) = ra1;
        *(uint4*)(sm + boff)      = rb;
        __syncthreads();
        if (c + 1 < NC){
            const int k1 = (c + 1) << 5;
            ra0 = *(const uint4*)(ap + k1);
            ra1 = *(const uint4*)(ap + k1 + 8);
            rb  = *(const uint4*)(bp + k1);
        }
        #pragma unroll
        for (int ks = 0; ks < 2; ks++){
            uint32_t ah[2][4], bh[2][4];
            #pragma unroll
            for (int mi = 0; mi < 2; mi++)
                ldsm_x4(ah[mi], a_base + mi*16*SSTR + ks*32);
            #pragma unroll
            for (int np = 0; np < 2; np++)
                ldsm_x4(bh[np], b_base + np*16*SSTR + ks*32);
            #pragma unroll
            for (int mi = 0; mi < 2; mi++)
                #pragma unroll
                for (int ni = 0; ni < 4; ni++){
                    const int np = ni >> 1, h = (ni & 1)*2;
                    mma16816h(acc[mi][ni], ah[mi], bh[np][h], bh[np][h+1]);
                }
        }
    }

    // ---- epilogue (r7 layout)
    const int sec = (MODE == 2) ? (n0 >> 8) : 0;
    #pragma unroll
    for (int mi = 0; mi < 2; mi++){
        const int rt0 = wm*32 + mi*16 + (lane >> 2);
        #pragma unroll
        for (int hf = 0; hf < 2; hf++){
            const int rt = rt0 + hf*8;
            const int m  = m0 + rt;
            if (m >= cnt) continue;
            const int pos = posBase + m;
            #pragma unroll
            for (int ni = 0; ni < 4; ni++){
                float v0 = acc[mi][ni][hf*2], v1 = acc[mi][ni][hf*2+1];
                const int col = n0 + wn*32 + (ni>>1)*16 + (ni&1)*8 + (lane&3)*2;
                if (MODE == 0){
                    *(float2*)(g_u + (size_t)pos*NST + col) = make_float2(v0, v1);
                } else if (MODE == 1){
                    float s0 = v0*sigmoidf_(v0), s1 = v1*sigmoidf_(v1);
                    *reinterpret_cast<uint32_t*>(g_shh + (size_t)pos*HID + col) =
                        h2bits(__floats2half2_rn(s0, s1));
                } else if (MODE == 2){
                    const int off = col & 255;
                    const size_t base = (size_t)pos*NST + off;
                    if (sec == 0){
                        *(float2*)(g_a + base) = make_float2(sigmoidf_(v0), sigmoidf_(v1));
                    } else if (sec == 1){
                        float2 u2 = *(const float2*)(g_u + base);
                        *(float2*)(g_bu + base) = make_float2(tanhf(v0)*u2.x, tanhf(v1)*u2.y);
                    } else if (sec == 2){
                        *(float2*)(g_c + base) = make_float2(tanhf(v0), tanhf(v1));
                    } else {
                        float2 u2 = *(const float2*)(g_u + base);
                        float2 d2 = *(const float2*)(dparam + e*NST + off);
                        *(float2*)(g_sk + base) =
                            make_float2(sigmoidf_(v0)*d2.x*u2.x, sigmoidf_(v1)*d2.y*u2.y);
                    }
                } else {
                    const int tok = g_list[pos];
                    *(float2*)(outp + (size_t)tok*DIM + col) = make_float2(v0, v1);
                }
            }
        }
    }
}

// ---------------- sequential scan, compact streaming, fp16 y ----------
__global__ void __launch_bounds__(256)
scan_kernel()
{
    const int b = blockIdx.x, e = blockIdx.y, tid = threadIdx.x;
    const int pos0 = g_beOff[b][e];
    const int n    = g_beCnt[b][e];

    float a[2][4], bu[2][4], cc[2][4], sk[2][4];
    #pragma unroll
    for (int j = 0; j < 4; j++){
        bool v = j < n;
        size_t idx = ((size_t)(pos0 + (v ? j : 0)))*NST + tid;
        a [0][j] = v ? g_a [idx] : 0.f;
        bu[0][j] = v ? g_bu[idx] : 0.f;
        cc[0][j] = v ? g_c [idx] : 0.f;
        sk[0][j] = v ? g_sk[idx] : 0.f;
    }

    float h = 0.f;
    int cur = 0;
    for (int base = 0; base < n; base += 4){
        const int nxt = cur ^ 1;
        #pragma unroll
        for (int j = 0; j < 4; j++){
            int i = base + 4 + j;
            if (i < n){
                size_t idx = ((size_t)(pos0 + i))*NST + tid;
                a [nxt][j] = g_a [idx];
                bu[nxt][j] = g_bu[idx];
                cc[nxt][j] = g_c [idx];
                sk[nxt][j] = g_sk[idx];
            }
        }
        #pragma unroll
        for (int j = 0; j < 4; j++){
            int i = base + j;
            if (i < n){
                h = fmaf(a[cur][j], h, bu[cur][j]);
                float y = fmaf(cc[cur][j], h, sk[cur][j]);
                g_yh[((size_t)(pos0 + i))*NST + tid] = __float2half(y);
            }
        }
        cur = nxt;
    }
}

// ---------------- launch ----------------
extern "C" void kernel_launch(void* const* d_in, const int* in_sizes, int n_in,
                              void* d_out, int out_size)
{
    const float* x     = (const float*)d_in[0];
    const int*   tok   = (const int*)  d_in[1];
    const float* Win   = (const float*)d_in[2];
    const float* Wsin  = (const float*)d_in[3];
    const float* Wsout = (const float*)d_in[4];
    const float* Wout  = (const float*)d_in[5];
    const float* dpar  = (const float*)d_in[6];
    float* outp = (float*)d_out;
    (void)in_sizes; (void)n_in; (void)out_size;

    __half *xg, *winh, *wsih, *wsoh, *woth, *shh, *yh;
    cudaGetSymbolAddress((void**)&xg,   g_xg);
    cudaGetSymbolAddress((void**)&winh, g_Winh);
    cudaGetSymbolAddress((void**)&wsih, g_Wsinh);
    cudaGetSymbolAddress((void**)&wsoh, g_Wsoh);
    cudaGetSymbolAddress((void**)&woth, g_Woth);
    cudaGetSymbolAddress((void**)&shh,  g_shh);
    cudaGetSymbolAddress((void**)&yh,   g_yh);

    // routing first (cvt_x gathers by g_list)
    count_kernel <<<64, 256>>>(tok);
    offset_kernel<<<1, 256>>>();
    place_kernel <<<64, 256>>>(tok);

    // conversions
    cvt_w<<<(NEXP*NST*DIM/4 + 255)/256, 256>>>(Win,   winh, NEXP*NST*DIM/4);
    cvt_w<<<(NEXP*HID*DIM/4 + 255)/256, 256>>>(Wsin,  wsih, NEXP*HID*DIM/4);
    cvt_w<<<(NEXP*4*NST*HID/4 + 255)/256, 256>>>(Wsout, wsoh, NEXP*4*NST*HID/4);
    cvt_w<<<(NEXP*DIM*NST/4 + 255)/256, 256>>>(Wout,  woth, NEXP*DIM*NST/4);
    cvt_x<<<NTOK, 256>>>(x);

    dim3 blk(256);
    // u = x . Win^T            (K=1024, nout=256)
    gemm_mma<0><<<dim3(20, 4,  NEXP), blk>>>(xg,  winh, nullptr, nullptr, DIM, NST);
    // sh = silu(x . Wsin^T)    (K=1024, nout=512)
    gemm_mma<1><<<dim3(20, 8,  NEXP), blk>>>(xg,  wsih, nullptr, nullptr, DIM, HID);
    // gates = sh . Wsout^T     (K=512,  nout=1024)
    gemm_mma<2><<<dim3(20, 16, NEXP), blk>>>(shh, wsoh, dpar,    nullptr, HID, 4*NST);
    // recurrence
    scan_kernel<<<dim3(BATCH, NEXP), 256>>>();
    // out = y . Wout^T         (K=256,  nout=1024)
    gemm_mma<3><<<dim3(20, 16, NEXP), blk>>>(yh,  woth, nullptr, outp,    NST, DIM);
}

// round 10
// speedup vs baseline: 1.6196x; 1.0757x over previous
#include <cuda_runtime.h>
#include <cuda_fp16.h>
#include <cstdint>

#define BATCH 8
#define SEQ   2048
#define DIM   1024
#define NST   256
#define HID   512
#define NEXP  8
#define NTOK  (BATCH*SEQ)   // 16384

// ---------------- device scratch (static, allocation-free) ----------------
__device__ __half g_xg[NTOK*DIM];                // x gathered to expert-compact order, fp16
__device__ __half g_Winh [NEXP*NST*DIM];
__device__ __half g_Wsinh[NEXP*HID*DIM];
__device__ __half g_Wsoh [NEXP*4*NST*HID];
__device__ __half g_Woth [NEXP*DIM*NST];
__device__ __half g_shh[NTOK*HID];               // silu out, fp16, compact
__device__ __half g_yh [NTOK*NST];               // scan out, fp16, compact
__device__ float g_u [NTOK*NST];
__device__ float g_a [NTOK*NST], g_bu[NTOK*NST], g_c[NTOK*NST], g_sk[NTOK*NST];
__device__ int g_list[NTOK];
__device__ int g_tileCnt[64][NEXP];
__device__ int g_tileOff[64][NEXP];
__device__ int g_eBase[NEXP];
__device__ int g_cnt[NEXP];
__device__ int g_beOff[BATCH][NEXP];
__device__ int g_beCnt[BATCH][NEXP];

__device__ __forceinline__ float sigmoidf_(float x){ return 1.f/(1.f+__expf(-x)); }

__device__ __forceinline__ uint32_t smem_u32(const void* p){
    uint32_t a;
    asm("{ .reg .u64 t; cvta.to.shared.u64 t, %1; cvt.u32.u64 %0, t; }" : "=r"(a) : "l"(p));
    return a;
}
__device__ __forceinline__ void ldsm_x4(uint32_t* r, uint32_t addr){
    asm volatile("ldmatrix.sync.aligned.m8n8.x4.shared.b16 {%0,%1,%2,%3}, [%4];"
        : "=r"(r[0]),"=r"(r[1]),"=r"(r[2]),"=r"(r[3]) : "r"(addr));
}
__device__ __forceinline__ void mma16816h(float* d, const uint32_t* a, uint32_t b0, uint32_t b1){
    asm volatile("mma.sync.aligned.m16n8k16.row.col.f32.f16.f16.f32 "
        "{%0,%1,%2,%3}, {%4,%5,%6,%7}, {%8,%9}, {%0,%1,%2,%3};"
        : "+f"(d[0]),"+f"(d[1]),"+f"(d[2]),"+f"(d[3])
        : "r"(a[0]),"r"(a[1]),"r"(a[2]),"r"(a[3]), "r"(b0),"r"(b1));
}
__device__ __forceinline__ uint32_t h2bits(__half2 h){ return *reinterpret_cast<uint32_t*>(&h); }
__device__ __forceinline__ int route_of(int tokid){
    unsigned x = (unsigned)tokid;
    x ^= x >> 16; x *= 2246822507u;
    x ^= x >> 13; x *= 3266489909u;
    x ^= x >> 16;
    return (int)(x & 7u);
}

// ---------------- deterministic routing (count / offset / place) ----------
__global__ void count_kernel(const int* __restrict__ tok){
    int blk = blockIdx.x, tid = threadIdx.x, wid = tid>>5, lane = tid&31;
    int r = route_of(tok[blk*256 + tid]);
    __shared__ int wcnt[8][8];
    unsigned m[8];
    #pragma unroll
    for (int e = 0; e < 8; e++) m[e] = __ballot_sync(0xffffffffu, r == e);
    if (lane < 8) wcnt[wid][lane] = __popc(m[lane]);
    __syncthreads();
    if (tid < 8){
        int s = 0;
        #pragma unroll
        for (int w = 0; w < 8; w++) s += wcnt[w][tid];
        g_tileCnt[blk][tid] = s;
    }
}
__global__ void offset_kernel(){
    __shared__ int tot[8];
    int tid = threadIdx.x;
    if (tid < 8){
        int run = 0;
        for (int t = 0; t < 64; t++){ g_tileOff[t][tid] = run; run += g_tileCnt[t][tid]; }
        tot[tid] = run;
    }
    __syncthreads();
    if (tid == 0){
        int base = 0;
        for (int e = 0; e < 8; e++){ g_eBase[e] = base; g_cnt[e] = tot[e]; base += tot[e]; }
    }
    __syncthreads();
    if (tid < 8){
        for (int t = 0; t < 64; t++) g_tileOff[t][tid] += g_eBase[tid];
        for (int b = 0; b < 8; b++){
            int s = 0;
            for (int k = 0; k < 8; k++) s += g_tileCnt[b*8+k][tid];
            g_beOff[b][tid] = g_tileOff[b*8][tid];
            g_beCnt[b][tid] = s;
        }
    }
}
__global__ void place_kernel(const int* __restrict__ tok){
    int blk = blockIdx.x, tid = threadIdx.x, wid = tid>>5, lane = tid&31;
    int t = blk*256 + tid;
    int r = route_of(tok[t]);
    __shared__ int wcnt[8][8];
    unsigned m[8];
    #pragma unroll
    for (int e = 0; e < 8; e++) m[e] = __ballot_sync(0xffffffffu, r == e);
    if (lane < 8) wcnt[wid][lane] = __popc(m[lane]);
    __syncthreads();
    int base = 0;
    for (int w = 0; w < wid; w++) base += wcnt[w][r];
    int rank = base + __popc(m[r] & ((1u << lane) - 1u));
    g_list[g_tileOff[blk][r] + rank] = t;
}

// ---------------- conversions (once per launch) ----------------
__global__ void __launch_bounds__(256)
cvt_w(const float* __restrict__ src, __half* __restrict__ dst, int n4){
    int i = blockIdx.x*blockDim.x + threadIdx.x;
    if (i >= n4) return;
    float4 v = reinterpret_cast<const float4*>(src)[i];
    reinterpret_cast<uint2*>(dst)[i] =
        make_uint2(h2bits(__floats2half2_rn(v.x, v.y)), h2bits(__floats2half2_rn(v.z, v.w)));
}
// x: gather into expert-compact order + round to fp16
__global__ void __launch_bounds__(256)
cvt_x(const float* __restrict__ x){
    const int pos = blockIdx.x;
    const int i   = threadIdx.x;               // float4 index within row (256 of them)
    const int tok = g_list[pos];
    float4 v = reinterpret_cast<const float4*>(x)[(size_t)tok*256 + i];
    reinterpret_cast<uint2*>(g_xg)[(size_t)pos*256 + i] =
        make_uint2(h2bits(__floats2half2_rn(v.x, v.y)), h2bits(__floats2half2_rn(v.z, v.w)));
}

// ---------------- grouped GEMM: KC=64, double-buffered, 1 sync/chunk ------
// C = A . W[e]^T ; A compact fp16 (pre-gathered), W fp16.
// 256 threads, CTA tile 128x64, warp tile 32x32, 2 CTAs/SM.
// MODE: 0 u, 1 silu->sh(fp16), 2 gates, 3 out proj (scatter via g_list)
#define SSTR   144                // 64 fp16 padded to 72 (144 B)
#define ATILE  (128*SSTR)         // 18432
#define BTILE  (64*SSTR)          // 9216
#define STAGE  (ATILE + BTILE)    // 27648 : A | B
#define GSMEM  (2*STAGE)          // 55296

template<int MODE>
__global__ void __launch_bounds__(256, 2)
gemm_mma(const __half* __restrict__ A, const __half* __restrict__ Wt,
         const float* __restrict__ dparam, float* __restrict__ outp,
         int K, int nout)
{
    const int e   = blockIdx.z;
    const int cnt = g_cnt[e];
    const int m0  = blockIdx.x * 128;
    if (m0 >= cnt) return;
    const int n0  = blockIdx.y * 64;
    const int posBase = g_eBase[e];
    const __half* __restrict__ W = Wt + (size_t)e * nout * K;

    extern __shared__ __align__(16) char sm[];

    const int tid  = threadIdx.x;
    const int wid  = tid >> 5;
    const int lane = tid & 31;

    // loader: A 128 rows, 2 threads/row (64B = 4 uint4 each); B 64 rows, 4 threads/row (32B = 2 uint4)
    const int arow = tid >> 1;
    const int acol = (tid & 1) * 32;           // halves
    int am = m0 + arow; if (am >= cnt) am = cnt - 1;
    const __half* ap = A + (size_t)(posBase + am)*K + acol;
    const int aoff = arow*SSTR + acol*2;

    const int brow = tid >> 2;
    const int bcol = (tid & 3) * 16;           // halves
    const __half* bp = W + (size_t)(n0 + brow)*K + bcol;
    const int boff = ATILE + brow*SSTR + bcol*2;

    const uint32_t sb = smem_u32(sm);
    const int wm = wid & 3, wn = wid >> 2;
    const uint32_t a_base = sb + (uint32_t)((wm*32 + (lane & 15))*SSTR + (lane >> 4)*16);
    const uint32_t b_base = sb + ATILE +
        (uint32_t)((wn*32 + (lane >> 4)*8 + (lane & 7))*SSTR + ((lane >> 3) & 1)*16);

    float acc[2][4][4];
    #pragma unroll
    for (int mi=0;mi<2;mi++)
        #pragma unroll
        for (int ni=0;ni<4;ni++)
            #pragma unroll
            for (int q=0;q<4;q++) acc[mi][ni][q]=0.f;

    const int NC = K >> 6;       // 64-wide chunks
    uint4 ra[4], rb[2];
    #pragma unroll
    for (int q = 0; q < 4; q++) ra[q] = *(const uint4*)(ap + q*8);
    #pragma unroll
    for (int q = 0; q < 2; q++) rb[q] = *(const uint4*)(bp + q*8);

    for (int c = 0; c < NC; c++){
        char* d = sm + (c & 1)*STAGE;
        *(uint4*)(d + aoff)      = ra[0];
        *(uint4*)(d + aoff + 16) = ra[1];
        *(uint4*)(d + aoff + 32) = ra[2];
        *(uint4*)(d + aoff + 48) = ra[3];
        *(uint4*)(d + boff)      = rb[0];
        *(uint4*)(d + boff + 16) = rb[1];
        __syncthreads();
        if (c + 1 < NC){
            const int k1 = (c + 1) << 6;
            #pragma unroll
            for (int q = 0; q < 4; q++) ra[q] = *(const uint4*)(ap + k1 + q*8);
            #pragma unroll
            for (int q = 0; q < 2; q++) rb[q] = *(const uint4*)(bp + k1 + q*8);
        }
        const uint32_t ab = a_base + (c & 1)*STAGE;
        const uint32_t bb = b_base + (c & 1)*STAGE;
        #pragma unroll
        for (int ks = 0; ks < 4; ks++){
            uint32_t ah[2][4], bh[2][4];
            #pragma unroll
            for (int mi = 0; mi < 2; mi++)
                ldsm_x4(ah[mi], ab + mi*16*SSTR + ks*32);
            #pragma unroll
            for (int np = 0; np < 2; np++)
                ldsm_x4(bh[np], bb + np*16*SSTR + ks*32);
            #pragma unroll
            for (int mi = 0; mi < 2; mi++)
                #pragma unroll
                for (int ni = 0; ni < 4; ni++){
                    const int np = ni >> 1, h = (ni & 1)*2;
                    mma16816h(acc[mi][ni], ah[mi], bh[np][h], bh[np][h+1]);
                }
        }
    }

    // ---- epilogue (r7/r9 layout)
    const int sec = (MODE == 2) ? (n0 >> 8) : 0;
    #pragma unroll
    for (int mi = 0; mi < 2; mi++){
        const int rt0 = wm*32 + mi*16 + (lane >> 2);
        #pragma unroll
        for (int hf = 0; hf < 2; hf++){
            const int rt = rt0 + hf*8;
            const int m  = m0 + rt;
            if (m >= cnt) continue;
            const int pos = posBase + m;
            #pragma unroll
            for (int ni = 0; ni < 4; ni++){
                float v0 = acc[mi][ni][hf*2], v1 = acc[mi][ni][hf*2+1];
                const int col = n0 + wn*32 + (ni>>1)*16 + (ni&1)*8 + (lane&3)*2;
                if (MODE == 0){
                    *(float2*)(g_u + (size_t)pos*NST + col) = make_float2(v0, v1);
                } else if (MODE == 1){
                    float s0 = v0*sigmoidf_(v0), s1 = v1*sigmoidf_(v1);
                    *reinterpret_cast<uint32_t*>(g_shh + (size_t)pos*HID + col) =
                        h2bits(__floats2half2_rn(s0, s1));
                } else if (MODE == 2){
                    const int off = col & 255;
                    const size_t base = (size_t)pos*NST + off;
                    if (sec == 0){
                        *(float2*)(g_a + base) = make_float2(sigmoidf_(v0), sigmoidf_(v1));
                    } else if (sec == 1){
                        float2 u2 = *(const float2*)(g_u + base);
                        *(float2*)(g_bu + base) = make_float2(tanhf(v0)*u2.x, tanhf(v1)*u2.y);
                    } else if (sec == 2){
                        *(float2*)(g_c + base) = make_float2(tanhf(v0), tanhf(v1));
                    } else {
                        float2 u2 = *(const float2*)(g_u + base);
                        float2 d2 = *(const float2*)(dparam + e*NST + off);
                        *(float2*)(g_sk + base) =
                            make_float2(sigmoidf_(v0)*d2.x*u2.x, sigmoidf_(v1)*d2.y*u2.y);
                    }
                } else {
                    const int tok = g_list[pos];
                    *(float2*)(outp + (size_t)tok*DIM + col) = make_float2(v0, v1);
                }
            }
        }
    }
}

// ---------------- sequential scan, compact streaming, fp16 y ----------
__global__ void __launch_bounds__(256)
scan_kernel()
{
    const int b = blockIdx.x, e = blockIdx.y, tid = threadIdx.x;
    const int pos0 = g_beOff[b][e];
    const int n    = g_beCnt[b][e];

    float a[2][4], bu[2][4], cc[2][4], sk[2][4];
    #pragma unroll
    for (int j = 0; j < 4; j++){
        bool v = j < n;
        size_t idx = ((size_t)(pos0 + (v ? j : 0)))*NST + tid;
        a [0][j] = v ? g_a [idx] : 0.f;
        bu[0][j] = v ? g_bu[idx] : 0.f;
        cc[0][j] = v ? g_c [idx] : 0.f;
        sk[0][j] = v ? g_sk[idx] : 0.f;
    }

    float h = 0.f;
    int cur = 0;
    for (int base = 0; base < n; base += 4){
        const int nxt = cur ^ 1;
        #pragma unroll
        for (int j = 0; j < 4; j++){
            int i = base + 4 + j;
            if (i < n){
                size_t idx = ((size_t)(pos0 + i))*NST + tid;
                a [nxt][j] = g_a [idx];
                bu[nxt][j] = g_bu[idx];
                cc[nxt][j] = g_c [idx];
                sk[nxt][j] = g_sk[idx];
            }
        }
        #pragma unroll
        for (int j = 0; j < 4; j++){
            int i = base + j;
            if (i < n){
                h = fmaf(a[cur][j], h, bu[cur][j]);
                float y = fmaf(cc[cur][j], h, sk[cur][j]);
                g_yh[((size_t)(pos0 + i))*NST + tid] = __float2half(y);
            }
        }
        cur = nxt;
    }
}

// ---------------- launch ----------------
extern "C" void kernel_launch(void* const* d_in, const int* in_sizes, int n_in,
                              void* d_out, int out_size)
{
    const float* x     = (const float*)d_in[0];
    const int*   tok   = (const int*)  d_in[1];
    const float* Win   = (const float*)d_in[2];
    const float* Wsin  = (const float*)d_in[3];
    const float* Wsout = (const float*)d_in[4];
    const float* Wout  = (const float*)d_in[5];
    const float* dpar  = (const float*)d_in[6];
    float* outp = (float*)d_out;
    (void)in_sizes; (void)n_in; (void)out_size;

    cudaFuncSetAttribute(gemm_mma<0>, cudaFuncAttributeMaxDynamicSharedMemorySize, GSMEM);
    cudaFuncSetAttribute(gemm_mma<1>, cudaFuncAttributeMaxDynamicSharedMemorySize, GSMEM);
    cudaFuncSetAttribute(gemm_mma<2>, cudaFuncAttributeMaxDynamicSharedMemorySize, GSMEM);
    cudaFuncSetAttribute(gemm_mma<3>, cudaFuncAttributeMaxDynamicSharedMemorySize, GSMEM);

    __half *xg, *winh, *wsih, *wsoh, *woth, *shh, *yh;
    cudaGetSymbolAddress((void**)&xg,   g_xg);
    cudaGetSymbolAddress((void**)&winh, g_Winh);
    cudaGetSymbolAddress((void**)&wsih, g_Wsinh);
    cudaGetSymbolAddress((void**)&wsoh, g_Wsoh);
    cudaGetSymbolAddress((void**)&woth, g_Woth);
    cudaGetSymbolAddress((void**)&shh,  g_shh);
    cudaGetSymbolAddress((void**)&yh,   g_yh);

    // routing first (cvt_x gathers by g_list)
    count_kernel <<<64, 256>>>(tok);
    offset_kernel<<<1, 256>>>();
    place_kernel <<<64, 256>>>(tok);

    // conversions
    cvt_w<<<(NEXP*NST*DIM/4 + 255)/256, 256>>>(Win,   winh, NEXP*NST*DIM/4);
    cvt_w<<<(NEXP*HID*DIM/4 + 255)/256, 256>>>(Wsin,  wsih, NEXP*HID*DIM/4);
    cvt_w<<<(NEXP*4*NST*HID/4 + 255)/256, 256>>>(Wsout, wsoh, NEXP*4*NST*HID/4);
    cvt_w<<<(NEXP*DIM*NST/4 + 255)/256, 256>>>(Wout,  woth, NEXP*DIM*NST/4);
    cvt_x<<<NTOK, 256>>>(x);

    dim3 blk(256);
    // u = x . Win^T            (K=1024, nout=256)
    gemm_mma<0><<<dim3(20, 4,  NEXP), blk, GSMEM>>>(xg,  winh, nullptr, nullptr, DIM, NST);
    // sh = silu(x . Wsin^T)    (K=1024, nout=512)
    gemm_mma<1><<<dim3(20, 8,  NEXP), blk, GSMEM>>>(xg,  wsih, nullptr, nullptr, DIM, HID);
    // gates = sh . Wsout^T     (K=512,  nout=1024)
    gemm_mma<2><<<dim3(20, 16, NEXP), blk, GSMEM>>>(shh, wsoh, dpar,    nullptr, HID, 4*NST);
    // recurrence
    scan_kernel<<<dim3(BATCH, NEXP), 256>>>();
    // out = y . Wout^T         (K=256,  nout=1024)
    gemm_mma<3><<<dim3(20, 16, NEXP), blk, GSMEM>>>(yh,  woth, nullptr, outp,    NST, DIM);
}

// round 11
// speedup vs baseline: 1.7600x; 1.0867x over previous
#include <cuda_runtime.h>
#include <cuda_fp16.h>
#include <cstdint>

#define BATCH 8
#define SEQ   2048
#define DIM   1024
#define NST   256
#define HID   512
#define NEXP  8
#define NTOK  (BATCH*SEQ)   // 16384

// ---------------- device scratch (static, allocation-free) ----------------
__device__ __half g_xg[NTOK*DIM];                // x gathered to expert-compact order, fp16
__device__ __half g_Winh [NEXP*NST*DIM];
__device__ __half g_Wsinh[NEXP*HID*DIM];
__device__ __half g_Wsoh [NEXP*4*NST*HID];
__device__ __half g_Woth [NEXP*DIM*NST];
__device__ __half g_shh[NTOK*HID];               // silu out, fp16, compact
__device__ __half g_yh [NTOK*NST];               // scan out, fp16, compact
__device__ float g_u [NTOK*NST];
__device__ float g_a [NTOK*NST], g_bu[NTOK*NST], g_c[NTOK*NST], g_sk[NTOK*NST];
__device__ int g_list[NTOK];
__device__ int g_tileCnt[64][NEXP];
__device__ int g_tileOff[64][NEXP];
__device__ int g_eBase[NEXP];
__device__ int g_cnt[NEXP];
__device__ int g_beOff[BATCH][NEXP];
__device__ int g_beCnt[BATCH][NEXP];

__device__ __forceinline__ float sigmoidf_(float x){ return 1.f/(1.f+__expf(-x)); }

__device__ __forceinline__ uint32_t smem_u32(const void* p){
    uint32_t a;
    asm("{ .reg .u64 t; cvta.to.shared.u64 t, %1; cvt.u32.u64 %0, t; }" : "=r"(a) : "l"(p));
    return a;
}
__device__ __forceinline__ void ldsm_x4(uint32_t* r, uint32_t addr){
    asm volatile("ldmatrix.sync.aligned.m8n8.x4.shared.b16 {%0,%1,%2,%3}, [%4];"
        : "=r"(r[0]),"=r"(r[1]),"=r"(r[2]),"=r"(r[3]) : "r"(addr));
}
__device__ __forceinline__ void mma16816h(float* d, const uint32_t* a, uint32_t b0, uint32_t b1){
    asm volatile("mma.sync.aligned.m16n8k16.row.col.f32.f16.f16.f32 "
        "{%0,%1,%2,%3}, {%4,%5,%6,%7}, {%8,%9}, {%0,%1,%2,%3};"
        : "+f"(d[0]),"+f"(d[1]),"+f"(d[2]),"+f"(d[3])
        : "r"(a[0]),"r"(a[1]),"r"(a[2]),"r"(a[3]), "r"(b0),"r"(b1));
}
__device__ __forceinline__ uint32_t h2bits(__half2 h){ return *reinterpret_cast<uint32_t*>(&h); }
__device__ __forceinline__ int route_of(int tokid){
    unsigned x = (unsigned)tokid;
    x ^= x >> 16; x *= 2246822507u;
    x ^= x >> 13; x *= 3266489909u;
    x ^= x >> 16;
    return (int)(x & 7u);
}

// ---------------- deterministic routing (count / offset / place) ----------
__global__ void count_kernel(const int* __restrict__ tok){
    int blk = blockIdx.x, tid = threadIdx.x, wid = tid>>5, lane = tid&31;
    int r = route_of(tok[blk*256 + tid]);
    __shared__ int wcnt[8][8];
    unsigned m[8];
    #pragma unroll
    for (int e = 0; e < 8; e++) m[e] = __ballot_sync(0xffffffffu, r == e);
    if (lane < 8) wcnt[wid][lane] = __popc(m[lane]);
    __syncthreads();
    if (tid < 8){
        int s = 0;
        #pragma unroll
        for (int w = 0; w < 8; w++) s += wcnt[w][tid];
        g_tileCnt[blk][tid] = s;
    }
}
__global__ void offset_kernel(){
    __shared__ int tot[8];
    int tid = threadIdx.x;
    if (tid < 8){
        int run = 0;
        for (int t = 0; t < 64; t++){ g_tileOff[t][tid] = run; run += g_tileCnt[t][tid]; }
        tot[tid] = run;
    }
    __syncthreads();
    if (tid == 0){
        int base = 0;
        for (int e = 0; e < 8; e++){ g_eBase[e] = base; g_cnt[e] = tot[e]; base += tot[e]; }
    }
    __syncthreads();
    if (tid < 8){
        for (int t = 0; t < 64; t++) g_tileOff[t][tid] += g_eBase[tid];
        for (int b = 0; b < 8; b++){
            int s = 0;
            for (int k = 0; k < 8; k++) s += g_tileCnt[b*8+k][tid];
            g_beOff[b][tid] = g_tileOff[b*8][tid];
            g_beCnt[b][tid] = s;
        }
    }
}
__global__ void place_kernel(const int* __restrict__ tok){
    int blk = blockIdx.x, tid = threadIdx.x, wid = tid>>5, lane = tid&31;
    int t = blk*256 + tid;
    int r = route_of(tok[t]);
    __shared__ int wcnt[8][8];
    unsigned m[8];
    #pragma unroll
    for (int e = 0; e < 8; e++) m[e] = __ballot_sync(0xffffffffu, r == e);
    if (lane < 8) wcnt[wid][lane] = __popc(m[lane]);
    __syncthreads();
    int base = 0;
    for (int w = 0; w < wid; w++) base += wcnt[w][r];
    int rank = base + __popc(m[r] & ((1u << lane) - 1u));
    g_list[g_tileOff[blk][r] + rank] = t;
}

// ---------------- conversions (once per launch) ----------------
// fused weight conversion: 4 arrays, range-dispatch by quad index
#define W0Q (NEXP*NST*DIM/4)        // 524288
#define W1Q (NEXP*HID*DIM/4)        // 1048576
#define W2Q (NEXP*4*NST*HID/4)      // 1048576
#define W3Q (NEXP*DIM*NST/4)        // 524288
#define WTOTQ (W0Q+W1Q+W2Q+W3Q)     // 3145728
__global__ void __launch_bounds__(256)
cvt_w_all(const float* __restrict__ s0, const float* __restrict__ s1,
          const float* __restrict__ s2, const float* __restrict__ s3)
{
    int i = blockIdx.x*blockDim.x + threadIdx.x;
    const float* src; __half* dst; int j = i;
    if (j < W0Q){ src = s0; dst = g_Winh; }
    else if ((j -= W0Q) < W1Q){ src = s1; dst = g_Wsinh; }
    else if ((j -= W1Q) < W2Q){ src = s2; dst = g_Wsoh; }
    else { j -= W2Q; src = s3; dst = g_Woth; }
    float4 v = reinterpret_cast<const float4*>(src)[j];
    reinterpret_cast<uint2*>(dst)[j] =
        make_uint2(h2bits(__floats2half2_rn(v.x, v.y)), h2bits(__floats2half2_rn(v.z, v.w)));
}
// x: gather into expert-compact order + round to fp16
__global__ void __launch_bounds__(256)
cvt_x(const float* __restrict__ x){
    const int pos = blockIdx.x;
    const int i   = threadIdx.x;               // float4 index within row (256 of them)
    const int tok = g_list[pos];
    float4 v = reinterpret_cast<const float4*>(x)[(size_t)tok*256 + i];
    reinterpret_cast<uint2*>(g_xg)[(size_t)pos*256 + i] =
        make_uint2(h2bits(__floats2half2_rn(v.x, v.y)), h2bits(__floats2half2_rn(v.z, v.w)));
}

// ---------------- grouped GEMM: 128x128 CTA tile, KC=64, 1 sync/chunk ----
// C = A . W[e]^T ; A compact fp16 (pre-gathered), W fp16.
// 256 threads, warp tile 64x32 (r3 mapping), double-buffered, 2 CTAs/SM.
// MODE: 0 u, 1 silu->sh(fp16), 2 gates, 3 out proj (scatter via g_list)
#define SSTR   144                // 64 fp16 padded to 72 (144 B)
#define ATILE  (128*SSTR)         // 18432
#define BTILE  (128*SSTR)         // 18432
#define STAGE  (ATILE + BTILE)    // 36864 : A | B
#define GSMEM  (2*STAGE)          // 73728

template<int MODE>
__global__ void __launch_bounds__(256, 2)
gemm_mma(const __half* __restrict__ A, const __half* __restrict__ Wt,
         const float* __restrict__ dparam, float* __restrict__ outp,
         int K, int nout)
{
    const int e   = blockIdx.z;
    const int cnt = g_cnt[e];
    const int m0  = blockIdx.x * 128;
    if (m0 >= cnt) return;
    const int n0  = blockIdx.y * 128;
    const int posBase = g_eBase[e];
    const __half* __restrict__ W = Wt + (size_t)e * nout * K;

    extern __shared__ __align__(16) char sm[];

    const int tid  = threadIdx.x;
    const int wid  = tid >> 5;
    const int lane = tid & 31;

    // loader: A and B each 128 rows, 2 threads/row, 64B (4 uint4) per thread
    const int lrow = tid >> 1;
    const int lcol = (tid & 1) * 32;           // halves
    int am = m0 + lrow; if (am >= cnt) am = cnt - 1;
    const __half* ap = A + (size_t)(posBase + am)*K + lcol;
    const __half* bp = W + (size_t)(n0 + lrow)*K + lcol;
    const int aoff = lrow*SSTR + lcol*2;
    const int boff = ATILE + aoff;

    const uint32_t sb = smem_u32(sm);
    const int wm = wid & 1, wn = wid >> 1;     // r3 warp mapping: 64x32 tiles
    const uint32_t a_base = sb + (uint32_t)((wm*64 + (lane & 15))*SSTR + (lane >> 4)*16);
    const uint32_t b_base = sb + ATILE +
        (uint32_t)((wn*32 + (lane >> 4)*8 + (lane & 7))*SSTR + ((lane >> 3) & 1)*16);

    float acc[4][4][4];
    #pragma unroll
    for (int mi=0;mi<4;mi++)
        #pragma unroll
        for (int ni=0;ni<4;ni++)
            #pragma unroll
            for (int q=0;q<4;q++) acc[mi][ni][q]=0.f;

    const int NC = K >> 6;       // 64-wide chunks
    uint4 ra[4], rb[4];
    #pragma unroll
    for (int q = 0; q < 4; q++){ ra[q] = *(const uint4*)(ap + q*8); rb[q] = *(const uint4*)(bp + q*8); }

    for (int c = 0; c < NC; c++){
        char* d = sm + (c & 1)*STAGE;
        #pragma unroll
        for (int q = 0; q < 4; q++){
            *(uint4*)(d + aoff + q*16) = ra[q];
            *(uint4*)(d + boff + q*16) = rb[q];
        }
        __syncthreads();
        if (c + 1 < NC){
            const int k1 = (c + 1) << 6;
            #pragma unroll
            for (int q = 0; q < 4; q++){
                ra[q] = *(const uint4*)(ap + k1 + q*8);
                rb[q] = *(const uint4*)(bp + k1 + q*8);
            }
        }
        const uint32_t ab = a_base + (c & 1)*STAGE;
        const uint32_t bb = b_base + (c & 1)*STAGE;
        #pragma unroll
        for (int ks = 0; ks < 4; ks++){
            uint32_t ah[4][4], bh[2][4];
            #pragma unroll
            for (int mi = 0; mi < 4; mi++)
                ldsm_x4(ah[mi], ab + mi*16*SSTR + ks*32);
            #pragma unroll
            for (int np = 0; np < 2; np++)
                ldsm_x4(bh[np], bb + np*16*SSTR + ks*32);
            #pragma unroll
            for (int mi = 0; mi < 4; mi++)
                #pragma unroll
                for (int ni = 0; ni < 4; ni++){
                    const int np = ni >> 1, h = (ni & 1)*2;
                    mma16816h(acc[mi][ni], ah[mi], bh[np][h], bh[np][h+1]);
                }
        }
    }

    // ---- epilogue (r3 layout: rows wm*64 + mi*16, cols wn*32)
    const int sec = (MODE == 2) ? (n0 >> 8) : 0;
    #pragma unroll
    for (int mi = 0; mi < 4; mi++){
        const int rt0 = wm*64 + mi*16 + (lane >> 2);
        #pragma unroll
        for (int hf = 0; hf < 2; hf++){
            const int rt = rt0 + hf*8;
            const int m  = m0 + rt;
            if (m >= cnt) continue;
            const int pos = posBase + m;
            #pragma unroll
            for (int ni = 0; ni < 4; ni++){
                float v0 = acc[mi][ni][hf*2], v1 = acc[mi][ni][hf*2+1];
                const int col = n0 + wn*32 + (ni>>1)*16 + (ni&1)*8 + (lane&3)*2;
                if (MODE == 0){
                    *(float2*)(g_u + (size_t)pos*NST + col) = make_float2(v0, v1);
                } else if (MODE == 1){
                    float s0 = v0*sigmoidf_(v0), s1 = v1*sigmoidf_(v1);
                    *reinterpret_cast<uint32_t*>(g_shh + (size_t)pos*HID + col) =
                        h2bits(__floats2half2_rn(s0, s1));
                } else if (MODE == 2){
                    const int off = col & 255;
                    const size_t base = (size_t)pos*NST + off;
                    if (sec == 0){
                        *(float2*)(g_a + base) = make_float2(sigmoidf_(v0), sigmoidf_(v1));
                    } else if (sec == 1){
                        float2 u2 = *(const float2*)(g_u + base);
                        *(float2*)(g_bu + base) = make_float2(tanhf(v0)*u2.x, tanhf(v1)*u2.y);
                    } else if (sec == 2){
                        *(float2*)(g_c + base) = make_float2(tanhf(v0), tanhf(v1));
                    } else {
                        float2 u2 = *(const float2*)(g_u + base);
                        float2 d2 = *(const float2*)(dparam + e*NST + off);
                        *(float2*)(g_sk + base) =
                            make_float2(sigmoidf_(v0)*d2.x*u2.x, sigmoidf_(v1)*d2.y*u2.y);
                    }
                } else {
                    const int tok = g_list[pos];
                    *(float2*)(outp + (size_t)tok*DIM + col) = make_float2(v0, v1);
                }
            }
        }
    }
}

// ---------------- sequential scan, compact streaming, fp16 y ----------
__global__ void __launch_bounds__(256)
scan_kernel()
{
    const int b = blockIdx.x, e = blockIdx.y, tid = threadIdx.x;
    const int pos0 = g_beOff[b][e];
    const int n    = g_beCnt[b][e];

    float a[2][4], bu[2][4], cc[2][4], sk[2][4];
    #pragma unroll
    for (int j = 0; j < 4; j++){
        bool v = j < n;
        size_t idx = ((size_t)(pos0 + (v ? j : 0)))*NST + tid;
        a [0][j] = v ? g_a [idx] : 0.f;
        bu[0][j] = v ? g_bu[idx] : 0.f;
        cc[0][j] = v ? g_c [idx] : 0.f;
        sk[0][j] = v ? g_sk[idx] : 0.f;
    }

    float h = 0.f;
    int cur = 0;
    for (int base = 0; base < n; base += 4){
        const int nxt = cur ^ 1;
        #pragma unroll
        for (int j = 0; j < 4; j++){
            int i = base + 4 + j;
            if (i < n){
                size_t idx = ((size_t)(pos0 + i))*NST + tid;
                a [nxt][j] = g_a [idx];
                bu[nxt][j] = g_bu[idx];
                cc[nxt][j] = g_c [idx];
                sk[nxt][j] = g_sk[idx];
            }
        }
        #pragma unroll
        for (int j = 0; j < 4; j++){
            int i = base + j;
            if (i < n){
                h = fmaf(a[cur][j], h, bu[cur][j]);
                float y = fmaf(cc[cur][j], h, sk[cur][j]);
                g_yh[((size_t)(pos0 + i))*NST + tid] = __float2half(y);
            }
        }
        cur = nxt;
    }
}

// ---------------- launch ----------------
extern "C" void kernel_launch(void* const* d_in, const int* in_sizes, int n_in,
                              void* d_out, int out_size)
{
    const float* x     = (const float*)d_in[0];
    const int*   tok   = (const int*)  d_in[1];
    const float* Win   = (const float*)d_in[2];
    const float* Wsin  = (const float*)d_in[3];
    const float* Wsout = (const float*)d_in[4];
    const float* Wout  = (const float*)d_in[5];
    const float* dpar  = (const float*)d_in[6];
    float* outp = (float*)d_out;
    (void)in_sizes; (void)n_in; (void)out_size;

    cudaFuncSetAttribute(gemm_mma<0>, cudaFuncAttributeMaxDynamicSharedMemorySize, GSMEM);
    cudaFuncSetAttribute(gemm_mma<1>, cudaFuncAttributeMaxDynamicSharedMemorySize, GSMEM);
    cudaFuncSetAttribute(gemm_mma<2>, cudaFuncAttributeMaxDynamicSharedMemorySize, GSMEM);
    cudaFuncSetAttribute(gemm_mma<3>, cudaFuncAttributeMaxDynamicSharedMemorySize, GSMEM);

    __half *xg, *shh, *yh;
    cudaGetSymbolAddress((void**)&xg,   g_xg);
    cudaGetSymbolAddress((void**)&shh,  g_shh);
    cudaGetSymbolAddress((void**)&yh,   g_yh);
    __half *winh, *wsih, *wsoh, *woth;
    cudaGetSymbolAddress((void**)&winh, g_Winh);
    cudaGetSymbolAddress((void**)&wsih, g_Wsinh);
    cudaGetSymbolAddress((void**)&wsoh, g_Wsoh);
    cudaGetSymbolAddress((void**)&woth, g_Woth);

    // routing first (cvt_x gathers by g_list)
    count_kernel <<<64, 256>>>(tok);
    offset_kernel<<<1, 256>>>();
    place_kernel <<<64, 256>>>(tok);

    // conversions (fused weights + gathered x)
    cvt_w_all<<<WTOTQ/256, 256>>>(Win, Wsin, Wsout, Wout);
    cvt_x<<<NTOK, 256>>>(x);

    dim3 blk(256);
    // u = x . Win^T            (K=1024, nout=256)
    gemm_mma<0><<<dim3(20, 2, NEXP), blk, GSMEM>>>(xg,  winh, nullptr, nullptr, DIM, NST);
    // sh = silu(x . Wsin^T)    (K=1024, nout=512)
    gemm_mma<1><<<dim3(20, 4, NEXP), blk, GSMEM>>>(xg,  wsih, nullptr, nullptr, DIM, HID);
    // gates = sh . Wsout^T     (K=512,  nout=1024)
    gemm_mma<2><<<dim3(20, 8, NEXP), blk, GSMEM>>>(shh, wsoh, dpar,    nullptr, HID, 4*NST);
    // recurrence
    scan_kernel<<<dim3(BATCH, NEXP), 256>>>();
    // out = y . Wout^T         (K=256,  nout=1024)
    gemm_mma<3><<<dim3(20, 8, NEXP), blk, GSMEM>>>(yh,  woth, nullptr, outp,    NST, DIM);
}